// round 15
// baseline (speedup 1.0000x reference)
#include <cuda_runtime.h>
#include <cuda_fp16.h>
#include <cstdint>

#define N_VOX 131072
#define CCH 128
#define NK 27
#define TMROWS 128
#define TPK (N_VOX / TMROWS)
#define KCAP 49152
#define WSZ (NK * CCH * CCH)
#define MAXTILES (NK * TPK)
#define CONV_GRID 296
#define CA_GRID 256                 // combine-act grid (co-resident: <=2/SM)
#define CA_VPB (N_VOX / CA_GRID)    // 512 voxels per block
#define EPSF 1e-4f
#define SLOPE_IN 0.05f
#define SLOPE_OUT (1.0f / 3.0f)

// ---------------- scratch (device globals) ----------------------------------
__device__ __half g_y[(size_t)N_VOX * CCH];
__device__ __half g_stage[(size_t)N_VOX * 27 * CCH];
__device__ __half g_x0[(size_t)N_VOX * CCH];
__device__ __half g_x1[(size_t)N_VOX * CCH];
__device__ __half g_wh[3 * WSZ];
__device__ int   g_pairs_j[NK * KCAP];
__device__ int   g_pairs_dst[NK * KCAP];
__device__ int   g_deg[N_VOX];
__device__ int   g_cnt[NK];
__device__ int   g_work[MAXTILES];
__device__ int   g_ntiles;
__device__ int   g_sync[3];
__device__ float g_sum[CCH], g_sumsq[CCH];

// ---------------- rulebook ----------------------------------------------------
__global__ void k_zero() {
    int i = blockIdx.x * 256 + threadIdx.x;
    if (i < N_VOX) g_deg[i] = 0;
    if (i < NK) g_cnt[i] = 0;
    if (i < 3) g_sync[i] = 0;
}

__global__ void k_fill(const int* __restrict__ nbr) {
    __shared__ int woff[8];
    __shared__ int sbase;
    int idx = blockIdx.x * 256 + threadIdx.x;
    int k = idx >> 17;
    int i = idx & (N_VOX - 1);
    if (k == 13) return;
    int j = nbr[i * NK + k];
    bool valid = (j >= 0);
    unsigned m = __ballot_sync(0xffffffffu, valid);
    int w = threadIdx.x >> 5, lane = threadIdx.x & 31;
    if (lane == 0) woff[w] = __popc(m);
    __syncthreads();
    if (threadIdx.x == 0) {
        int o = 0;
        for (int q = 0; q < 8; ++q) { int c = woff[q]; woff[q] = o; o += c; }
        sbase = o ? atomicAdd(&g_cnt[k], o) : 0;
    }
    __syncthreads();
    if (valid) {
        int pos = k * KCAP + sbase + woff[w] + __popc(m & ((1u << lane) - 1u));
        g_pairs_j[pos] = j;
        int d = atomicAdd(&g_deg[i], 1);
        g_pairs_dst[pos] = i * 27 + d;
    }
}

__global__ void k_worklist() {
    __shared__ int tk[NK], base[NK];
    int tid = threadIdx.x;
    if (tid < NK)
        tk[tid] = (tid == 13) ? TPK : ((g_cnt[tid] + TMROWS - 1) >> 7);
    __syncthreads();
    if (tid == 0) {
        int o = 0;
        for (int k = 0; k < NK; ++k) { base[k] = o; o += tk[k]; }
        g_ntiles = o;
    }
    __syncthreads();
    for (int k = 0; k < NK; ++k)
        for (int t = tid; t < tk[k]; t += 256)
            g_work[base[k] + t] = (k << 16) | t;
}

// ---------------- fp16 conversions ----------------------------------------------
__global__ void k_wsplit(const float* __restrict__ w1, const float* __restrict__ w2,
                         const float* __restrict__ w3) {
    int i = blockIdx.x * blockDim.x + threadIdx.x;
    const float* src = (blockIdx.y == 0) ? w1 : (blockIdx.y == 1 ? w2 : w3);
    g_wh[blockIdx.y * WSZ + i] = __float2half(src[i]);
}

__global__ void k_xsplit(const float* __restrict__ F, __half* X) {
    int idx = blockIdx.x * blockDim.x + threadIdx.x;
    float4 v = *(const float4*)(F + (size_t)idx * 4);
    __half2* x = (__half2*)X;
    x[idx * 2]     = __floats2half2_rn(v.x, v.y);
    x[idx * 2 + 1] = __floats2half2_rn(v.z, v.w);
}

// ---------------- mma.sync helpers ----------------------------------------------
__device__ __forceinline__ void mma16816(float* d, const unsigned* a, const unsigned* b) {
    asm volatile(
        "mma.sync.aligned.m16n8k16.row.col.f32.f16.f16.f32 "
        "{%0,%1,%2,%3}, {%4,%5,%6,%7}, {%8,%9}, {%0,%1,%2,%3};"
        : "+f"(d[0]), "+f"(d[1]), "+f"(d[2]), "+f"(d[3])
        : "r"(a[0]), "r"(a[1]), "r"(a[2]), "r"(a[3]), "r"(b[0]), "r"(b[1]));
}

#define LDSM_X4(R, addr) asm volatile( \
    "ldmatrix.sync.aligned.m8n8.x4.shared.b16 {%0,%1,%2,%3}, [%4];" \
    : "=r"((R)[0]), "=r"((R)[1]), "=r"((R)[2]), "=r"((R)[3]) : "r"(addr))
#define LDSM_X4T(R, addr) asm volatile( \
    "ldmatrix.sync.aligned.m8n8.x4.trans.shared.b16 {%0,%1,%2,%3}, [%4];" \
    : "=r"((R)[0]), "=r"((R)[1]), "=r"((R)[2]), "=r"((R)[3]) : "r"(addr))

__device__ __forceinline__ void cp16(unsigned dst, const void* src, int srcsize) {
    asm volatile("cp.async.cg.shared.global [%0], [%1], 16, %2;"
                 :: "r"(dst), "l"(src), "r"(srcsize) : "memory");
}
#define CP_COMMIT() asm volatile("cp.async.commit_group;" ::: "memory")
#define CP_WAIT1() asm volatile("cp.async.wait_group 1;" ::: "memory")
#define CP_WAIT0() asm volatile("cp.async.wait_group 0;" ::: "memory")

// ---------------- SMEM layout (dynamic, bytes) -----------------------------------
#define SM_A 0
#define SM_B 24576
#define SM_SJ 57344
#define SM_SD 57856
#define SMEM_BYTES 58880

__device__ __forceinline__ unsigned swz(int row, int g) {
    return (unsigned)(row * 256 + ((g ^ (row & 7)) << 4));
}
__device__ __forceinline__ unsigned swzA(int row, int g) {
    return (unsigned)(row * 64 + ((g ^ ((row >> 1) & 3)) << 4));
}

// Persistent conv: grid = CONV_GRID, contiguous work-list partition per block.
__global__ void __launch_bounds__(256, 2) conv_mma(
    const __half* __restrict__ X,
    const __half* __restrict__ Wh,
    __half* __restrict__ Ystage)
{
    extern __shared__ char dsm[];
    unsigned sb = (unsigned)__cvta_generic_to_shared(dsm);
    int tid = threadIdx.x;

    if (blockIdx.x == 0 && tid < CCH) {
        g_sum[tid] = 0.f;
        g_sumsq[tid] = 0.f;
    }

    int total = g_ntiles;
    int per = (total + gridDim.x - 1) / gridDim.x;
    int lo = blockIdx.x * per;
    int hi = min(lo + per, total);

    int lane = tid & 31, warp = tid >> 5;
    int wm = warp & 3, wn = warp >> 2;
    int arow = wm * 32 + (lane & 15);
    int brow = lane & 15;
    int gsel = lane >> 4;
    int gr = lane >> 2, gc = (lane & 3) * 2;

    int* sj = (int*)(dsm + SM_SJ);
    int kprev = -1;

    for (int itm = lo; itm < hi; ++itm) {
        int wk = g_work[itm];
        int k = wk >> 16;
        int t = wk & 0xFFFF;
        int m0 = t * TMROWS;
        int cnt = (k == 13) ? N_VOX : g_cnt[k];
        int obase = k * KCAP + m0;
        int rows = min(TMROWS, cnt - m0);
        const __half* Whk = Wh + k * CCH * CCH;

        int* sd = (int*)(dsm + SM_SD + (itm & 1) * 512);

        if (tid < TMROWS) {
            int j = -1, d = 0;
            if (tid < rows) {
                if (k == 13) {
                    j = m0 + tid;
                    d = j * 27 + g_deg[j];
                } else {
                    j = g_pairs_j[obase + tid];
                    d = g_pairs_dst[obase + tid];
                }
            }
            sj[tid] = j;
            sd[tid] = d;
        }
        __syncthreads();

        if (k != kprev) {
            kprev = k;
#pragma unroll
            for (int it2 = 0; it2 < 8; ++it2) {
                int u = it2 * 256 + tid;
                int c = u >> 9;
                int rem = u & 511;
                int row = rem >> 4;
                int seg = rem & 15;
                const __half* src = Whk + (size_t)(c * 32 + row) * CCH + seg * 8;
                cp16(sb + SM_B + c * 8192 + swz(row, seg), src, 16);
            }
            CP_COMMIT();
        }
#pragma unroll
        for (int c = 0; c < 2; ++c) {
#pragma unroll
            for (int it2 = 0; it2 < 2; ++it2) {
                int u = it2 * 256 + tid;
                int row = u >> 2;
                int g = u & 3;
                int j = sj[row];
                const __half* src = X + (size_t)max(j, 0) * CCH + c * 32 + g * 8;
                cp16(sb + SM_A + c * 8192 + swzA(row, g), src, j >= 0 ? 16 : 0);
            }
            CP_COMMIT();
        }

        float acc[2][8][4];
#pragma unroll
        for (int mi = 0; mi < 2; ++mi)
#pragma unroll
            for (int ni = 0; ni < 8; ++ni)
#pragma unroll
                for (int q = 0; q < 4; ++q) acc[mi][ni][q] = 0.f;

#pragma unroll
        for (int kc = 0; kc < 4; ++kc) {
            if (kc < 3) { CP_WAIT1(); } else { CP_WAIT0(); }
            __syncthreads();
            if (kc < 2) {
                int c = kc + 2;
                int s = c % 3;
#pragma unroll
                for (int it2 = 0; it2 < 2; ++it2) {
                    int u = it2 * 256 + tid;
                    int row = u >> 2;
                    int g = u & 3;
                    int j = sj[row];
                    const __half* src = X + (size_t)max(j, 0) * CCH + c * 32 + g * 8;
                    cp16(sb + SM_A + s * 8192 + swzA(row, g), src, j >= 0 ? 16 : 0);
                }
                CP_COMMIT();
            }
            unsigned aa = sb + SM_A + (kc % 3) * 8192;
            unsigned bb = sb + SM_B + kc * 8192;
#pragma unroll
            for (int kk = 0; kk < 2; ++kk) {
                unsigned ahf[2][4];
                int gA = kk * 2 + gsel;
#pragma unroll
                for (int mi = 0; mi < 2; ++mi) {
                    int R = arow + mi * 16;
                    LDSM_X4(ahf[mi], aa + swzA(R, gA));
                }
                int rB = kk * 16 + brow;
#pragma unroll
                for (int n2 = 0; n2 < 4; ++n2) {
                    int gB = wn * 8 + n2 * 2 + gsel;
                    unsigned boff = swz(rB, gB);
                    unsigned bhf[4];
                    LDSM_X4T(bhf, bb + boff);
#pragma unroll
                    for (int mi = 0; mi < 2; ++mi) {
                        mma16816(acc[mi][n2 * 2],     ahf[mi], bhf);
                        mma16816(acc[mi][n2 * 2 + 1], ahf[mi], bhf + 2);
                    }
                }
            }
        }

        // epilogue: unified fp16 scatter to stage dst slots
#pragma unroll
        for (int mi = 0; mi < 2; ++mi)
#pragma unroll
            for (int ni = 0; ni < 8; ++ni) {
                int c = wn * 64 + ni * 8 + gc;
                int r0 = wm * 32 + mi * 16 + gr;
                if (r0 < rows)
                    *(__half2*)(Ystage + (size_t)sd[r0] * CCH + c) =
                        __floats2half2_rn(acc[mi][ni][0], acc[mi][ni][1]);
                int r1 = r0 + 8;
                if (r1 < rows)
                    *(__half2*)(Ystage + (size_t)sd[r1] * CCH + c) =
                        __floats2half2_rn(acc[mi][ni][2], acc[mi][ni][3]);
            }
    }
}

// ---------------- fused combine + BN stats + grid-sync + activation -------------
// Phase 1: sum deg+1 contiguous stage rows -> fp16 y, block stats -> atomicAdd.
// Grid barrier via g_sync[layer] (CA_GRID=256 blocks, <=2/SM => co-resident).
// Phase 2: recompute scale/shift, act on OWN voxels (y is L2-hot), write x / out.
__global__ void __launch_bounds__(256, 2) k_combine_act(
    __half* __restrict__ Y,
    const float* __restrict__ gma, const float* __restrict__ bta,
    __half* __restrict__ Xout,                       // inner layers
    const __half* __restrict__ RH, float* __restrict__ O,  // final layer
    int layer, int is_final)
{
    __shared__ float red[8][CCH];
    __shared__ float ssc[CCH], ssh[CCH];
    int tid = threadIdx.x;
    int warp = tid >> 5, lane = tid & 31;
    int vbase = blockIdx.x * CA_VPB + warp * (CA_VPB / 8);   // 64 voxels per warp

    float s[4] = {0.f, 0.f, 0.f, 0.f}, s2[4] = {0.f, 0.f, 0.f, 0.f};
    for (int tt = 0; tt < CA_VPB / 8; ++tt) {
        int v = vbase + tt;
        int degp = g_deg[v] + 1;
        float4 acc = make_float4(0.f, 0.f, 0.f, 0.f);
        const __half2* base = (const __half2*)(g_stage + (size_t)v * 27 * CCH + lane * 4);
        for (int q = 0; q < degp; ++q) {
            const __half2* p = base + q * (CCH / 2);
            float2 a = __half22float2(p[0]);
            float2 b = __half22float2(p[1]);
            acc.x += a.x; acc.y += a.y; acc.z += b.x; acc.w += b.y;
        }
        __half2* yv = (__half2*)(Y + (size_t)v * CCH);
        yv[lane * 2]     = __floats2half2_rn(acc.x, acc.y);
        yv[lane * 2 + 1] = __floats2half2_rn(acc.z, acc.w);
        s[0] += acc.x; s[1] += acc.y; s[2] += acc.z; s[3] += acc.w;
        s2[0] += acc.x * acc.x; s2[1] += acc.y * acc.y;
        s2[2] += acc.z * acc.z; s2[3] += acc.w * acc.w;
    }
#pragma unroll
    for (int q = 0; q < 4; ++q) red[warp][lane * 4 + q] = s[q];
    __syncthreads();
    if (tid < CCH) {
        float tot = 0.f;
#pragma unroll
        for (int w = 0; w < 8; ++w) tot += red[w][tid];
        atomicAdd(&g_sum[tid], tot);
    }
    __syncthreads();
#pragma unroll
    for (int q = 0; q < 4; ++q) red[warp][lane * 4 + q] = s2[q];
    __syncthreads();
    if (tid < CCH) {
        float tot = 0.f;
#pragma unroll
        for (int w = 0; w < 8; ++w) tot += red[w][tid];
        atomicAdd(&g_sumsq[tid], tot);
    }

    // ---- grid barrier ----
    __syncthreads();
    if (tid == 0) {
        __threadfence();
        atomicAdd(&g_sync[layer], 1);
        while (*(volatile int*)&g_sync[layer] < (int)gridDim.x) { }
    }
    __syncthreads();
    __threadfence();

    // ---- phase 2: BN finalize + activation on own voxels ----
    if (tid < CCH) {
        float mu = g_sum[tid] * (1.0f / N_VOX);
        float var = g_sumsq[tid] * (1.0f / N_VOX) - mu * mu;
        float rs = rsqrtf(var + EPSF);
        float sc = gma[tid] * rs;
        ssc[tid] = sc;
        ssh[tid] = bta[tid] - mu * sc;
    }
    __syncthreads();

    int c4 = lane * 4;
    float4 sc = *(const float4*)(ssc + c4);
    float4 sh = *(const float4*)(ssh + c4);
    for (int tt = 0; tt < CA_VPB / 8; ++tt) {
        int v = vbase + tt;
        const __half2* yv = (const __half2*)(Y + (size_t)v * CCH + c4);
        float2 y0 = __half22float2(yv[0]), y1 = __half22float2(yv[1]);
        float4 o;
        o.x = fmaf(y0.x, sc.x, sh.x);
        o.y = fmaf(y0.y, sc.y, sh.y);
        o.z = fmaf(y1.x, sc.z, sh.z);
        o.w = fmaf(y1.y, sc.w, sh.w);
        if (is_final) {
            const __half2* rh = (const __half2*)(RH + (size_t)v * CCH + c4);
            float2 r0 = __half22float2(rh[0]), r1 = __half22float2(rh[1]);
            o.x += r0.x; o.y += r0.y; o.z += r1.x; o.w += r1.y;
            o.x = o.x >= 0.f ? o.x : SLOPE_OUT * o.x;
            o.y = o.y >= 0.f ? o.y : SLOPE_OUT * o.y;
            o.z = o.z >= 0.f ? o.z : SLOPE_OUT * o.z;
            o.w = o.w >= 0.f ? o.w : SLOPE_OUT * o.w;
            *(float4*)(O + (size_t)v * CCH + c4) = o;
        } else {
            o.x = o.x >= 0.f ? o.x : SLOPE_IN * o.x;
            o.y = o.y >= 0.f ? o.y : SLOPE_IN * o.y;
            o.z = o.z >= 0.f ? o.z : SLOPE_IN * o.z;
            o.w = o.w >= 0.f ? o.w : SLOPE_IN * o.w;
            __half2* x = (__half2*)(Xout + (size_t)v * CCH + c4);
            x[0] = __floats2half2_rn(o.x, o.y);
            x[1] = __floats2half2_rn(o.z, o.w);
        }
    }
}

// ---------------- launch ----------------------------------------------------------------
extern "C" void kernel_launch(void* const* d_in, const int* in_sizes, int n_in,
                              void* d_out, int out_size) {
    const float* feat = (const float*)d_in[0];
    const int*   nbr  = (const int*)d_in[1];
    const float* w1   = (const float*)d_in[2];
    const float* w2   = (const float*)d_in[3];
    const float* w3   = (const float*)d_in[4];
    const float* g1   = (const float*)d_in[5];
    const float* b1   = (const float*)d_in[6];
    const float* g2   = (const float*)d_in[7];
    const float* b2   = (const float*)d_in[8];
    const float* g3   = (const float*)d_in[9];
    const float* b3   = (const float*)d_in[10];
    float* out = (float*)d_out;

    __half *p_y, *p_stage, *p_x0, *p_x1, *p_wh;
    cudaGetSymbolAddress((void**)&p_y, g_y);
    cudaGetSymbolAddress((void**)&p_stage, g_stage);
    cudaGetSymbolAddress((void**)&p_x0, g_x0);
    cudaGetSymbolAddress((void**)&p_x1, g_x1);
    cudaGetSymbolAddress((void**)&p_wh, g_wh);

    cudaFuncSetAttribute(conv_mma, cudaFuncAttributeMaxDynamicSharedMemorySize,
                         SMEM_BYTES);

    const int nelem4 = (N_VOX * CCH) / 4;
    const int act_grid = nelem4 / 256;

    // rulebook + operand prep
    k_zero<<<N_VOX / 256, 256>>>();
    k_fill<<<(NK * N_VOX) / 256, 256>>>(nbr);
    k_worklist<<<1, 256>>>();
    {
        dim3 wg(WSZ / 256, 3);
        k_wsplit<<<wg, 256>>>(w1, w2, w3);
    }
    k_xsplit<<<act_grid, 256>>>(feat, p_x0);

    // ---- layer 1 ----
    conv_mma<<<CONV_GRID, 256, SMEM_BYTES>>>(p_x0, p_wh, p_stage);
    k_combine_act<<<CA_GRID, 256>>>(p_y, g1, b1, p_x1, nullptr, nullptr, 0, 0);

    // ---- layer 2 ----
    conv_mma<<<CONV_GRID, 256, SMEM_BYTES>>>(p_x1, p_wh + WSZ, p_stage);
    k_combine_act<<<CA_GRID, 256>>>(p_y, g2, b2, p_x0, nullptr, nullptr, 1, 0);

    // ---- layer 3 ----
    conv_mma<<<CONV_GRID, 256, SMEM_BYTES>>>(p_x0, p_wh + 2 * WSZ, p_stage);
    k_combine_act<<<CA_GRID, 256>>>(p_y, g3, b3, nullptr, p_x1, out, 2, 1);
}

// round 16
// speedup vs baseline: 1.3202x; 1.3202x over previous
#include <cuda_runtime.h>
#include <cuda_fp16.h>
#include <cstdint>

#define N_VOX 131072
#define CCH 128
#define NK 27
#define TMROWS 128
#define TPK (N_VOX / TMROWS)
#define KCAP 49152
#define WSZ (NK * CCH * CCH)
#define MAXTILES (NK * TPK)
#define CONV_GRID 304
#define EPSF 1e-4f
#define SLOPE_IN 0.05f
#define SLOPE_OUT (1.0f / 3.0f)

// ---------------- scratch (device globals) ----------------------------------
__device__ __half g_y[(size_t)N_VOX * CCH];
__device__ __half g_stage[(size_t)N_VOX * 27 * CCH];
__device__ __half g_x0[(size_t)N_VOX * CCH];
__device__ __half g_x1[(size_t)N_VOX * CCH];
__device__ __half g_wh[3 * WSZ];
__device__ int   g_pairs_j[NK * KCAP];
__device__ int   g_pairs_dst[NK * KCAP];
__device__ int   g_deg[N_VOX];
__device__ int   g_cnt[NK];
__device__ int   g_work[MAXTILES];
__device__ int   g_ntiles;
__device__ float g_sum[CCH], g_sumsq[CCH];

// ---------------- rulebook ----------------------------------------------------
__global__ void k_zero() {
    int i = blockIdx.x * 256 + threadIdx.x;
    if (i < N_VOX) g_deg[i] = 0;
    if (i < NK) g_cnt[i] = 0;
}

__global__ void k_fill(const int* __restrict__ nbr) {
    __shared__ int woff[8];
    __shared__ int sbase;
    int idx = blockIdx.x * 256 + threadIdx.x;
    int k = idx >> 17;
    int i = idx & (N_VOX - 1);
    if (k == 13) return;
    int j = nbr[i * NK + k];
    bool valid = (j >= 0);
    unsigned m = __ballot_sync(0xffffffffu, valid);
    int w = threadIdx.x >> 5, lane = threadIdx.x & 31;
    if (lane == 0) woff[w] = __popc(m);
    __syncthreads();
    if (threadIdx.x == 0) {
        int o = 0;
        for (int q = 0; q < 8; ++q) { int c = woff[q]; woff[q] = o; o += c; }
        sbase = o ? atomicAdd(&g_cnt[k], o) : 0;
    }
    __syncthreads();
    if (valid) {
        int pos = k * KCAP + sbase + woff[w] + __popc(m & ((1u << lane) - 1u));
        g_pairs_j[pos] = j;
        int d = atomicAdd(&g_deg[i], 1);
        g_pairs_dst[pos] = i * 27 + d;
    }
}

__global__ void k_worklist() {
    __shared__ int tk[NK], base[NK];
    int tid = threadIdx.x;
    if (tid < NK)
        tk[tid] = (tid == 13) ? TPK : ((g_cnt[tid] + TMROWS - 1) >> 7);
    __syncthreads();
    if (tid == 0) {
        int o = 0;
        for (int k = 0; k < NK; ++k) { base[k] = o; o += tk[k]; }
        g_ntiles = o;
    }
    __syncthreads();
    for (int k = 0; k < NK; ++k)
        for (int t = tid; t < tk[k]; t += 256)
            g_work[base[k] + t] = (k << 16) | t;
}

// ---------------- fp16 conversions ----------------------------------------------
__global__ void k_wsplit(const float* __restrict__ w1, const float* __restrict__ w2,
                         const float* __restrict__ w3) {
    int i = blockIdx.x * blockDim.x + threadIdx.x;
    const float* src = (blockIdx.y == 0) ? w1 : (blockIdx.y == 1 ? w2 : w3);
    g_wh[blockIdx.y * WSZ + i] = __float2half(src[i]);
}

__global__ void k_xsplit(const float* __restrict__ F, __half* X) {
    int idx = blockIdx.x * blockDim.x + threadIdx.x;
    float4 v = *(const float4*)(F + (size_t)idx * 4);
    __half2* x = (__half2*)X;
    x[idx * 2]     = __floats2half2_rn(v.x, v.y);
    x[idx * 2 + 1] = __floats2half2_rn(v.z, v.w);
}

// ---------------- mma.sync helpers ----------------------------------------------
__device__ __forceinline__ void mma16816(float* d, const unsigned* a, const unsigned* b) {
    asm volatile(
        "mma.sync.aligned.m16n8k16.row.col.f32.f16.f16.f32 "
        "{%0,%1,%2,%3}, {%4,%5,%6,%7}, {%8,%9}, {%0,%1,%2,%3};"
        : "+f"(d[0]), "+f"(d[1]), "+f"(d[2]), "+f"(d[3])
        : "r"(a[0]), "r"(a[1]), "r"(a[2]), "r"(a[3]), "r"(b[0]), "r"(b[1]));
}

#define LDSM_X4(R, addr) asm volatile( \
    "ldmatrix.sync.aligned.m8n8.x4.shared.b16 {%0,%1,%2,%3}, [%4];" \
    : "=r"((R)[0]), "=r"((R)[1]), "=r"((R)[2]), "=r"((R)[3]) : "r"(addr))
#define LDSM_X4T(R, addr) asm volatile( \
    "ldmatrix.sync.aligned.m8n8.x4.trans.shared.b16 {%0,%1,%2,%3}, [%4];" \
    : "=r"((R)[0]), "=r"((R)[1]), "=r"((R)[2]), "=r"((R)[3]) : "r"(addr))

__device__ __forceinline__ void cp16(unsigned dst, const void* src, int srcsize) {
    asm volatile("cp.async.cg.shared.global [%0], [%1], 16, %2;"
                 :: "r"(dst), "l"(src), "r"(srcsize) : "memory");
}
#define CP_COMMIT() asm volatile("cp.async.commit_group;" ::: "memory")
#define CP_WAIT1() asm volatile("cp.async.wait_group 1;" ::: "memory")
#define CP_WAIT0() asm volatile("cp.async.wait_group 0;" ::: "memory")

// ---------------- SMEM layout (dynamic, bytes) -----------------------------------
#define SM_A 0
#define SM_B 24576
#define SM_SJ 57344
#define SM_SD 57856
#define SMEM_BYTES 58880

__device__ __forceinline__ unsigned swz(int row, int g) {
    return (unsigned)(row * 256 + ((g ^ (row & 7)) << 4));
}
__device__ __forceinline__ unsigned swzA(int row, int g) {
    return (unsigned)(row * 64 + ((g ^ ((row >> 1) & 3)) << 4));
}

// Persistent conv: grid = CONV_GRID, contiguous work-list partition per block.
// Next-tile (j,d) rulebook entries are register-prefetched one tile ahead.
__global__ void __launch_bounds__(256, 2) conv_mma(
    const __half* __restrict__ X,
    const __half* __restrict__ Wh,
    __half* __restrict__ Ystage)
{
    extern __shared__ char dsm[];
    unsigned sb = (unsigned)__cvta_generic_to_shared(dsm);
    int tid = threadIdx.x;

    if (blockIdx.x == 0 && tid < CCH) {
        g_sum[tid] = 0.f;
        g_sumsq[tid] = 0.f;
    }

    int total = g_ntiles;
    int per = (total + gridDim.x - 1) / gridDim.x;
    int lo = blockIdx.x * per;
    int hi = min(lo + per, total);
    if (lo >= hi) return;

    int lane = tid & 31, warp = tid >> 5;
    int wm = warp & 3, wn = warp >> 2;
    int arow = wm * 32 + (lane & 15);
    int brow = lane & 15;
    int gsel = lane >> 4;
    int gr = lane >> 2, gc = (lane & 3) * 2;

    int* sj = (int*)(dsm + SM_SJ);
    int kprev = -1;

    // register preload for the first tile
    int jn = -1, dn = 0;
    if (tid < TMROWS) {
        int wk0 = g_work[lo];
        int k0 = wk0 >> 16, t0 = wk0 & 0xFFFF;
        int m00 = t0 * TMROWS;
        int cnt0 = (k0 == 13) ? N_VOX : g_cnt[k0];
        if (tid < min(TMROWS, cnt0 - m00)) {
            if (k0 == 13) { jn = m00 + tid; dn = jn * 27 + g_deg[jn]; }
            else {
                int ob = k0 * KCAP + m00;
                jn = g_pairs_j[ob + tid];
                dn = g_pairs_dst[ob + tid];
            }
        }
    }

    for (int itm = lo; itm < hi; ++itm) {
        int wk = g_work[itm];
        int k = wk >> 16;
        int t = wk & 0xFFFF;
        int m0 = t * TMROWS;
        int cnt = (k == 13) ? N_VOX : g_cnt[k];
        int rows = min(TMROWS, cnt - m0);
        const __half* Whk = Wh + k * CCH * CCH;

        int* sd = (int*)(dsm + SM_SD + (itm & 1) * 512);

        if (tid < TMROWS) {
            sj[tid] = jn;
            sd[tid] = dn;
        }
        __syncthreads();

        // register-prefetch next tile's (j,d) — latency hidden under this tile
        jn = -1; dn = 0;
        if (itm + 1 < hi && tid < TMROWS) {
            int wk1 = g_work[itm + 1];
            int k1 = wk1 >> 16, t1 = wk1 & 0xFFFF;
            int m01 = t1 * TMROWS;
            int cnt1 = (k1 == 13) ? N_VOX : g_cnt[k1];
            if (tid < min(TMROWS, cnt1 - m01)) {
                if (k1 == 13) { jn = m01 + tid; dn = jn * 27 + g_deg[jn]; }
                else {
                    int ob1 = k1 * KCAP + m01;
                    jn = g_pairs_j[ob1 + tid];
                    dn = g_pairs_dst[ob1 + tid];
                }
            }
        }

        if (k != kprev) {
            kprev = k;
#pragma unroll
            for (int it2 = 0; it2 < 8; ++it2) {
                int u = it2 * 256 + tid;
                int c = u >> 9;
                int rem = u & 511;
                int row = rem >> 4;
                int seg = rem & 15;
                const __half* src = Whk + (size_t)(c * 32 + row) * CCH + seg * 8;
                cp16(sb + SM_B + c * 8192 + swz(row, seg), src, 16);
            }
            CP_COMMIT();
        }
#pragma unroll
        for (int c = 0; c < 2; ++c) {
#pragma unroll
            for (int it2 = 0; it2 < 2; ++it2) {
                int u = it2 * 256 + tid;
                int row = u >> 2;
                int g = u & 3;
                int j = sj[row];
                const __half* src = X + (size_t)max(j, 0) * CCH + c * 32 + g * 8;
                cp16(sb + SM_A + c * 8192 + swzA(row, g), src, j >= 0 ? 16 : 0);
            }
            CP_COMMIT();
        }

        float acc[2][8][4];
#pragma unroll
        for (int mi = 0; mi < 2; ++mi)
#pragma unroll
            for (int ni = 0; ni < 8; ++ni)
#pragma unroll
                for (int q = 0; q < 4; ++q) acc[mi][ni][q] = 0.f;

#pragma unroll
        for (int kc = 0; kc < 4; ++kc) {
            if (kc < 3) { CP_WAIT1(); } else { CP_WAIT0(); }
            __syncthreads();
            if (kc < 2) {
                int c = kc + 2;
                int s = c % 3;
#pragma unroll
                for (int it2 = 0; it2 < 2; ++it2) {
                    int u = it2 * 256 + tid;
                    int row = u >> 2;
                    int g = u & 3;
                    int j = sj[row];
                    const __half* src = X + (size_t)max(j, 0) * CCH + c * 32 + g * 8;
                    cp16(sb + SM_A + s * 8192 + swzA(row, g), src, j >= 0 ? 16 : 0);
                }
                CP_COMMIT();
            }
            unsigned aa = sb + SM_A + (kc % 3) * 8192;
            unsigned bb = sb + SM_B + kc * 8192;
#pragma unroll
            for (int kk = 0; kk < 2; ++kk) {
                unsigned ahf[2][4];
                int gA = kk * 2 + gsel;
#pragma unroll
                for (int mi = 0; mi < 2; ++mi) {
                    int R = arow + mi * 16;
                    LDSM_X4(ahf[mi], aa + swzA(R, gA));
                }
                int rB = kk * 16 + brow;
#pragma unroll
                for (int n2 = 0; n2 < 4; ++n2) {
                    int gB = wn * 8 + n2 * 2 + gsel;
                    unsigned boff = swz(rB, gB);
                    unsigned bhf[4];
                    LDSM_X4T(bhf, bb + boff);
#pragma unroll
                    for (int mi = 0; mi < 2; ++mi) {
                        mma16816(acc[mi][n2 * 2],     ahf[mi], bhf);
                        mma16816(acc[mi][n2 * 2 + 1], ahf[mi], bhf + 2);
                    }
                }
            }
        }

        // epilogue: unified fp16 scatter to stage dst slots
#pragma unroll
        for (int mi = 0; mi < 2; ++mi)
#pragma unroll
            for (int ni = 0; ni < 8; ++ni) {
                int c = wn * 64 + ni * 8 + gc;
                int r0 = wm * 32 + mi * 16 + gr;
                if (r0 < rows)
                    *(__half2*)(Ystage + (size_t)sd[r0] * CCH + c) =
                        __floats2half2_rn(acc[mi][ni][0], acc[mi][ni][1]);
                int r1 = r0 + 8;
                if (r1 < rows)
                    *(__half2*)(Ystage + (size_t)sd[r1] * CCH + c) =
                        __floats2half2_rn(acc[mi][ni][2], acc[mi][ni][3]);
            }
    }
}

// ---------------- combine staged rows -> fp16 y + BN stats -----------------------
__global__ void __launch_bounds__(256) k_combine(__half* __restrict__ Y) {
    __shared__ float red[8][CCH];
    int warp = threadIdx.x >> 5, lane = threadIdx.x & 31;
    float s[4] = {0.f, 0.f, 0.f, 0.f}, s2[4] = {0.f, 0.f, 0.f, 0.f};
    int vbase = blockIdx.x * 64 + warp * 8;
    for (int tt = 0; tt < 8; ++tt) {
        int v = vbase + tt;
        int degp = g_deg[v] + 1;
        float4 acc = make_float4(0.f, 0.f, 0.f, 0.f);
        const __half2* base = (const __half2*)(g_stage + (size_t)v * 27 * CCH + lane * 4);
        for (int q = 0; q < degp; ++q) {
            const __half2* p = base + q * (CCH / 2);
            float2 a = __half22float2(p[0]);
            float2 b = __half22float2(p[1]);
            acc.x += a.x; acc.y += a.y; acc.z += b.x; acc.w += b.y;
        }
        __half2* yv = (__half2*)(Y + (size_t)v * CCH);
        yv[lane * 2]     = __floats2half2_rn(acc.x, acc.y);
        yv[lane * 2 + 1] = __floats2half2_rn(acc.z, acc.w);
        s[0] += acc.x; s[1] += acc.y; s[2] += acc.z; s[3] += acc.w;
        s2[0] += acc.x * acc.x; s2[1] += acc.y * acc.y;
        s2[2] += acc.z * acc.z; s2[3] += acc.w * acc.w;
    }
#pragma unroll
    for (int q = 0; q < 4; ++q) red[warp][lane * 4 + q] = s[q];
    __syncthreads();
    if (threadIdx.x < CCH) {
        float tot = 0.f;
#pragma unroll
        for (int w = 0; w < 8; ++w) tot += red[w][threadIdx.x];
        atomicAdd(&g_sum[threadIdx.x], tot);
    }
    __syncthreads();
#pragma unroll
    for (int q = 0; q < 4; ++q) red[warp][lane * 4 + q] = s2[q];
    __syncthreads();
    if (threadIdx.x < CCH) {
        float tot = 0.f;
#pragma unroll
        for (int w = 0; w < 8; ++w) tot += red[w][threadIdx.x];
        atomicAdd(&g_sumsq[threadIdx.x], tot);
    }
}

// ---------------- activations (BN finalize fused in-block) --------------------------
__global__ void k_act_inner(const __half* __restrict__ Y,
                            const float* __restrict__ gma, const float* __restrict__ bta,
                            __half* __restrict__ X) {
    __shared__ float ssc[CCH], ssh[CCH];
    if (threadIdx.x < CCH) {
        float mu = g_sum[threadIdx.x] * (1.0f / N_VOX);
        float var = g_sumsq[threadIdx.x] * (1.0f / N_VOX) - mu * mu;
        float rs = rsqrtf(var + EPSF);
        float sc = gma[threadIdx.x] * rs;
        ssc[threadIdx.x] = sc;
        ssh[threadIdx.x] = bta[threadIdx.x] - mu * sc;
    }
    __syncthreads();
    int idx = blockIdx.x * blockDim.x + threadIdx.x;
    int c4 = (idx & 31) << 2;
    const __half2* yv = (const __half2*)(Y + (size_t)idx * 4);
    float2 y0 = __half22float2(yv[0]), y1 = __half22float2(yv[1]);
    float4 sc = *(const float4*)(ssc + c4);
    float4 sh = *(const float4*)(ssh + c4);
    float4 v;
    v.x = fmaf(y0.x, sc.x, sh.x);
    v.y = fmaf(y0.y, sc.y, sh.y);
    v.z = fmaf(y1.x, sc.z, sh.z);
    v.w = fmaf(y1.y, sc.w, sh.w);
    v.x = v.x >= 0.f ? v.x : SLOPE_IN * v.x;
    v.y = v.y >= 0.f ? v.y : SLOPE_IN * v.y;
    v.z = v.z >= 0.f ? v.z : SLOPE_IN * v.z;
    v.w = v.w >= 0.f ? v.w : SLOPE_IN * v.w;
    __half2* x = (__half2*)X;
    x[idx * 2]     = __floats2half2_rn(v.x, v.y);
    x[idx * 2 + 1] = __floats2half2_rn(v.z, v.w);
}

__global__ void k_act_out(const __half* __restrict__ Y,
                          const float* __restrict__ gma, const float* __restrict__ bta,
                          const __half* __restrict__ RH, float* __restrict__ O) {
    __shared__ float ssc[CCH], ssh[CCH];
    if (threadIdx.x < CCH) {
        float mu = g_sum[threadIdx.x] * (1.0f / N_VOX);
        float var = g_sumsq[threadIdx.x] * (1.0f / N_VOX) - mu * mu;
        float rs = rsqrtf(var + EPSF);
        float sc = gma[threadIdx.x] * rs;
        ssc[threadIdx.x] = sc;
        ssh[threadIdx.x] = bta[threadIdx.x] - mu * sc;
    }
    __syncthreads();
    int idx = blockIdx.x * blockDim.x + threadIdx.x;
    int c4 = (idx & 31) << 2;
    const __half2* yv = (const __half2*)(Y + (size_t)idx * 4);
    float2 y0 = __half22float2(yv[0]), y1 = __half22float2(yv[1]);
    const __half2* rh = (const __half2*)(RH + (size_t)idx * 4);
    float2 r0 = __half22float2(rh[0]), r1 = __half22float2(rh[1]);
    float4 sc = *(const float4*)(ssc + c4);
    float4 sh = *(const float4*)(ssh + c4);
    float4 v;
    v.x = fmaf(y0.x, sc.x, sh.x) + r0.x;
    v.y = fmaf(y0.y, sc.y, sh.y) + r0.y;
    v.z = fmaf(y1.x, sc.z, sh.z) + r1.x;
    v.w = fmaf(y1.y, sc.w, sh.w) + r1.y;
    v.x = v.x >= 0.f ? v.x : SLOPE_OUT * v.x;
    v.y = v.y >= 0.f ? v.y : SLOPE_OUT * v.y;
    v.z = v.z >= 0.f ? v.z : SLOPE_OUT * v.z;
    v.w = v.w >= 0.f ? v.w : SLOPE_OUT * v.w;
    *(float4*)(O + (size_t)idx * 4) = v;
}

// ---------------- launch ----------------------------------------------------------------
extern "C" void kernel_launch(void* const* d_in, const int* in_sizes, int n_in,
                              void* d_out, int out_size) {
    const float* feat = (const float*)d_in[0];
    const int*   nbr  = (const int*)d_in[1];
    const float* w1   = (const float*)d_in[2];
    const float* w2   = (const float*)d_in[3];
    const float* w3   = (const float*)d_in[4];
    const float* g1   = (const float*)d_in[5];
    const float* b1   = (const float*)d_in[6];
    const float* g2   = (const float*)d_in[7];
    const float* b2   = (const float*)d_in[8];
    const float* g3   = (const float*)d_in[9];
    const float* b3   = (const float*)d_in[10];
    float* out = (float*)d_out;

    __half *p_y, *p_stage, *p_x0, *p_x1, *p_wh;
    cudaGetSymbolAddress((void**)&p_y, g_y);
    cudaGetSymbolAddress((void**)&p_stage, g_stage);
    cudaGetSymbolAddress((void**)&p_x0, g_x0);
    cudaGetSymbolAddress((void**)&p_x1, g_x1);
    cudaGetSymbolAddress((void**)&p_wh, g_wh);

    cudaFuncSetAttribute(conv_mma, cudaFuncAttributeMaxDynamicSharedMemorySize,
                         SMEM_BYTES);

    const int nelem4 = (N_VOX * CCH) / 4;
    const int act_grid = nelem4 / 256;
    const int comb_grid = N_VOX / 64;          // 2048

    // rulebook + operand prep
    k_zero<<<N_VOX / 256, 256>>>();
    k_fill<<<(NK * N_VOX) / 256, 256>>>(nbr);
    k_worklist<<<1, 256>>>();
    {
        dim3 wg(WSZ / 256, 3);
        k_wsplit<<<wg, 256>>>(w1, w2, w3);
    }
    k_xsplit<<<act_grid, 256>>>(feat, p_x0);

    // ---- layer 1 ----
    conv_mma<<<CONV_GRID, 256, SMEM_BYTES>>>(p_x0, p_wh, p_stage);
    k_combine<<<comb_grid, 256>>>(p_y);
    k_act_inner<<<act_grid, 256>>>(p_y, g1, b1, p_x1);   // act1 = residual

    // ---- layer 2 ----
    conv_mma<<<CONV_GRID, 256, SMEM_BYTES>>>(p_x1, p_wh + WSZ, p_stage);
    k_combine<<<comb_grid, 256>>>(p_y);
    k_act_inner<<<act_grid, 256>>>(p_y, g2, b2, p_x0);   // ping-pong

    // ---- layer 3 ----
    conv_mma<<<CONV_GRID, 256, SMEM_BYTES>>>(p_x0, p_wh + 2 * WSZ, p_stage);
    k_combine<<<comb_grid, 256>>>(p_y);
    k_act_out<<<act_grid, 256>>>(p_y, g3, b3, p_x1, out);
}

// round 17
// speedup vs baseline: 1.3778x; 1.0437x over previous
#include <cuda_runtime.h>
#include <cuda_fp16.h>
#include <cstdint>

#define N_VOX 131072
#define CCH 128
#define NK 27
#define TMROWS 128
#define TPK (N_VOX / TMROWS)
#define KCAP 49152
#define WSZ (NK * CCH * CCH)
#define MAXTILES (NK * TPK)
#define CONV_GRID 304
#define EPSF 1e-4f
#define SLOPE_IN 0.05f
#define SLOPE_OUT (1.0f / 3.0f)

// ---------------- scratch (device globals) ----------------------------------
__device__ __half g_y[(size_t)N_VOX * CCH];
__device__ __half g_stage[(size_t)N_VOX * 27 * CCH];
__device__ __half g_x0[(size_t)N_VOX * CCH];
__device__ __half g_x1[(size_t)N_VOX * CCH];
__device__ __half g_wh[3 * WSZ];
__device__ int   g_pairs_j[NK * KCAP];
__device__ int   g_pairs_dst[NK * KCAP];
__device__ int   g_deg[N_VOX];
__device__ int   g_cnt[NK];
__device__ int   g_work[MAXTILES];
__device__ int   g_ntiles;
__device__ float g_sum[CCH], g_sumsq[CCH];

// ---------------- rulebook ----------------------------------------------------
__global__ void k_zero() {
    int i = blockIdx.x * 256 + threadIdx.x;
    if (i < N_VOX) g_deg[i] = 0;
    if (i < NK) g_cnt[i] = 0;
}

__global__ void k_fill(const int* __restrict__ nbr) {
    __shared__ int woff[8];
    __shared__ int sbase;
    int idx = blockIdx.x * 256 + threadIdx.x;
    int k = idx >> 17;
    int i = idx & (N_VOX - 1);
    if (k == 13) return;
    int j = nbr[i * NK + k];
    bool valid = (j >= 0);
    unsigned m = __ballot_sync(0xffffffffu, valid);
    int w = threadIdx.x >> 5, lane = threadIdx.x & 31;
    if (lane == 0) woff[w] = __popc(m);
    __syncthreads();
    if (threadIdx.x == 0) {
        int o = 0;
        for (int q = 0; q < 8; ++q) { int c = woff[q]; woff[q] = o; o += c; }
        sbase = o ? atomicAdd(&g_cnt[k], o) : 0;
    }
    __syncthreads();
    if (valid) {
        int pos = k * KCAP + sbase + woff[w] + __popc(m & ((1u << lane) - 1u));
        g_pairs_j[pos] = j;
        int d = atomicAdd(&g_deg[i], 1);
        g_pairs_dst[pos] = i * 27 + d;
    }
}

__global__ void k_worklist() {
    __shared__ int tk[NK], base[NK];
    int tid = threadIdx.x;
    if (tid < NK)
        tk[tid] = (tid == 13) ? TPK : ((g_cnt[tid] + TMROWS - 1) >> 7);
    __syncthreads();
    if (tid == 0) {
        int o = 0;
        for (int k = 0; k < NK; ++k) { base[k] = o; o += tk[k]; }
        g_ntiles = o;
    }
    __syncthreads();
    for (int k = 0; k < NK; ++k)
        for (int t = tid; t < tk[k]; t += 256)
            g_work[base[k] + t] = (k << 16) | t;
}

// ---------------- fp16 conversions ----------------------------------------------
__global__ void k_wsplit(const float* __restrict__ w1, const float* __restrict__ w2,
                         const float* __restrict__ w3) {
    int i = blockIdx.x * blockDim.x + threadIdx.x;
    const float* src = (blockIdx.y == 0) ? w1 : (blockIdx.y == 1 ? w2 : w3);
    g_wh[blockIdx.y * WSZ + i] = __float2half(src[i]);
}

__global__ void k_xsplit(const float* __restrict__ F, __half* X) {
    int idx = blockIdx.x * blockDim.x + threadIdx.x;
    float4 v = *(const float4*)(F + (size_t)idx * 4);
    __half2* x = (__half2*)X;
    x[idx * 2]     = __floats2half2_rn(v.x, v.y);
    x[idx * 2 + 1] = __floats2half2_rn(v.z, v.w);
}

// ---------------- mma.sync helpers ----------------------------------------------
__device__ __forceinline__ void mma16816(float* d, const unsigned* a, const unsigned* b) {
    asm volatile(
        "mma.sync.aligned.m16n8k16.row.col.f32.f16.f16.f32 "
        "{%0,%1,%2,%3}, {%4,%5,%6,%7}, {%8,%9}, {%0,%1,%2,%3};"
        : "+f"(d[0]), "+f"(d[1]), "+f"(d[2]), "+f"(d[3])
        : "r"(a[0]), "r"(a[1]), "r"(a[2]), "r"(a[3]), "r"(b[0]), "r"(b[1]));
}

#define LDSM_X4(R, addr) asm volatile( \
    "ldmatrix.sync.aligned.m8n8.x4.shared.b16 {%0,%1,%2,%3}, [%4];" \
    : "=r"((R)[0]), "=r"((R)[1]), "=r"((R)[2]), "=r"((R)[3]) : "r"(addr))
#define LDSM_X4T(R, addr) asm volatile( \
    "ldmatrix.sync.aligned.m8n8.x4.trans.shared.b16 {%0,%1,%2,%3}, [%4];" \
    : "=r"((R)[0]), "=r"((R)[1]), "=r"((R)[2]), "=r"((R)[3]) : "r"(addr))

__device__ __forceinline__ void cp16(unsigned dst, const void* src, int srcsize) {
    asm volatile("cp.async.cg.shared.global [%0], [%1], 16, %2;"
                 :: "r"(dst), "l"(src), "r"(srcsize) : "memory");
}
#define CP_COMMIT() asm volatile("cp.async.commit_group;" ::: "memory")
#define CP_WAIT1() asm volatile("cp.async.wait_group 1;" ::: "memory")
#define CP_WAIT0() asm volatile("cp.async.wait_group 0;" ::: "memory")

// ---------------- SMEM layout (dynamic, bytes) -----------------------------------
// A: 2 x 32KB (whole-tile double buffer). B: 32KB. sj/sd: 2 x 512B each.
#define SM_A 0
#define SM_B 65536
#define SM_SJ 98304
#define SM_SD 99328
#define SMEM_BYTES 100352

__device__ __forceinline__ unsigned swz(int row, int g) {
    return (unsigned)(row * 256 + ((g ^ (row & 7)) << 4));
}
__device__ __forceinline__ unsigned swzA(int row, int g) {
    return (unsigned)(row * 64 + ((g ^ ((row >> 1) & 3)) << 4));
}

// Persistent conv, cross-tile pipelined: A for tile n+1 gathers during tile n's
// compute (2x32KB A parity buffers); sj/sd parity-buffered; 2 barriers/tile.
__global__ void __launch_bounds__(256, 2) conv_mma(
    const __half* __restrict__ X,
    const __half* __restrict__ Wh,
    __half* __restrict__ Ystage)
{
    extern __shared__ char dsm[];
    unsigned sb = (unsigned)__cvta_generic_to_shared(dsm);
    int tid = threadIdx.x;

    if (blockIdx.x == 0 && tid < CCH) {
        g_sum[tid] = 0.f;
        g_sumsq[tid] = 0.f;
    }

    int total = g_ntiles;
    int per = (total + gridDim.x - 1) / gridDim.x;
    int lo = blockIdx.x * per;
    int hi = min(lo + per, total);
    if (lo >= hi) return;

    int lane = tid & 31, warp = tid >> 5;
    int wm = warp & 3, wn = warp >> 2;
    int arow = wm * 32 + (lane & 15);
    int brow = lane & 15;
    int gsel = lane >> 4;
    int gr = lane >> 2, gc = (lane & 3) * 2;

    // decode helper (inlined twice below)
    // ---- preamble: tile lo ----
    int wk0 = g_work[lo];
    int kprev = wk0 >> 16;
    {
        int t0 = wk0 & 0xFFFF;
        int m00 = t0 * TMROWS;
        int cnt0 = (kprev == 13) ? N_VOX : g_cnt[kprev];
        int j = -1, d = 0;
        if (tid < TMROWS && tid < min(TMROWS, cnt0 - m00)) {
            if (kprev == 13) { j = m00 + tid; d = j * 27 + g_deg[j]; }
            else {
                int ob = kprev * KCAP + m00;
                j = g_pairs_j[ob + tid];
                d = g_pairs_dst[ob + tid];
            }
        }
        if (tid < TMROWS) {
            ((int*)(dsm + SM_SJ + (lo & 1) * 512))[tid] = j;
            ((int*)(dsm + SM_SD + (lo & 1) * 512))[tid] = d;
        }
    }
    // register prefetch: tile lo+1
    int jn = -1, dn = 0;
    if (lo + 1 < hi && tid < TMROWS) {
        int wk1 = g_work[lo + 1];
        int k1 = wk1 >> 16, t1 = wk1 & 0xFFFF;
        int m01 = t1 * TMROWS;
        int cnt1 = (k1 == 13) ? N_VOX : g_cnt[k1];
        if (tid < min(TMROWS, cnt1 - m01)) {
            if (k1 == 13) { jn = m01 + tid; dn = jn * 27 + g_deg[jn]; }
            else {
                int ob1 = k1 * KCAP + m01;
                jn = g_pairs_j[ob1 + tid];
                dn = g_pairs_dst[ob1 + tid];
            }
        }
    }
    __syncthreads();
    // issue B(k(lo)) + A(lo) as one group
    {
        const __half* Whk = Wh + kprev * CCH * CCH;
#pragma unroll
        for (int it2 = 0; it2 < 8; ++it2) {
            int u = it2 * 256 + tid;
            int c = u >> 9;
            int rem = u & 511;
            int row = rem >> 4;
            int seg = rem & 15;
            cp16(sb + SM_B + c * 8192 + swz(row, seg),
                 Whk + (size_t)(c * 32 + row) * CCH + seg * 8, 16);
        }
        const int* sj0 = (const int*)(dsm + SM_SJ + (lo & 1) * 512);
#pragma unroll
        for (int it2 = 0; it2 < 8; ++it2) {
            int u = it2 * 256 + tid;
            int c = u >> 9;
            int rem = u & 511;
            int row = rem >> 2;
            int g = rem & 3;
            int j = sj0[row];
            cp16(sb + SM_A + (lo & 1) * 32768 + c * 8192 + swzA(row, g),
                 X + (size_t)max(j, 0) * CCH + c * 32 + g * 8, j >= 0 ? 16 : 0);
        }
        CP_COMMIT();
    }

    for (int itm = lo; itm < hi; ++itm) {
        int p = itm & 1;
        int wk = g_work[itm];
        int k = wk >> 16;
        int t = wk & 0xFFFF;
        int m0 = t * TMROWS;
        int cnt = (k == 13) ? N_VOX : g_cnt[k];
        int rows = min(TMROWS, cnt - m0);

        CP_WAIT0();           // A(itm) [+ anything older] complete
        __syncthreads();      // (1) visible to all; prior tile's reads done

        bool bload = (k != kprev);
        if (bload) {          // rare: new weight tile (prior compute done)
            kprev = k;
            const __half* Whk = Wh + k * CCH * CCH;
#pragma unroll
            for (int it2 = 0; it2 < 8; ++it2) {
                int u = it2 * 256 + tid;
                int c = u >> 9;
                int rem = u & 511;
                int row = rem >> 4;
                int seg = rem & 15;
                cp16(sb + SM_B + c * 8192 + swz(row, seg),
                     Whk + (size_t)(c * 32 + row) * CCH + seg * 8, 16);
            }
            CP_COMMIT();
        }

        bool havenext = (itm + 1 < hi);
        if (havenext && tid < TMROWS) {
            ((int*)(dsm + SM_SJ + (p ^ 1) * 512))[tid] = jn;
            ((int*)(dsm + SM_SD + (p ^ 1) * 512))[tid] = dn;
        }
        // register prefetch tile itm+2
        int jn2 = -1, dn2 = 0;
        if (itm + 2 < hi && tid < TMROWS) {
            int wk2 = g_work[itm + 2];
            int k2 = wk2 >> 16, t2 = wk2 & 0xFFFF;
            int m02 = t2 * TMROWS;
            int cnt2 = (k2 == 13) ? N_VOX : g_cnt[k2];
            if (tid < min(TMROWS, cnt2 - m02)) {
                if (k2 == 13) { jn2 = m02 + tid; dn2 = jn2 * 27 + g_deg[jn2]; }
                else {
                    int ob2 = k2 * KCAP + m02;
                    jn2 = g_pairs_j[ob2 + tid];
                    dn2 = g_pairs_dst[ob2 + tid];
                }
            }
        }
        __syncthreads();      // (2) next sj/sd visible

        if (havenext) {       // issue A(itm+1) into the other buffer
            const int* sjn = (const int*)(dsm + SM_SJ + (p ^ 1) * 512);
#pragma unroll
            for (int it2 = 0; it2 < 8; ++it2) {
                int u = it2 * 256 + tid;
                int c = u >> 9;
                int rem = u & 511;
                int row = rem >> 2;
                int g = rem & 3;
                int j = sjn[row];
                cp16(sb + SM_A + (p ^ 1) * 32768 + c * 8192 + swzA(row, g),
                     X + (size_t)max(j, 0) * CCH + c * 32 + g * 8, j >= 0 ? 16 : 0);
            }
            CP_COMMIT();
        }
        if (bload) {          // B must complete before compute (A(itm+1) may stay pending)
            if (havenext) { CP_WAIT1(); } else { CP_WAIT0(); }
            __syncthreads();
        }
        jn = jn2; dn = dn2;

        // ---- compute: straight-line, no barriers ----
        float acc[2][8][4];
#pragma unroll
        for (int mi = 0; mi < 2; ++mi)
#pragma unroll
            for (int ni = 0; ni < 8; ++ni)
#pragma unroll
                for (int q = 0; q < 4; ++q) acc[mi][ni][q] = 0.f;

        unsigned abase = sb + SM_A + p * 32768;
#pragma unroll
        for (int kc = 0; kc < 4; ++kc) {
            unsigned aa = abase + kc * 8192;
            unsigned bb = sb + SM_B + kc * 8192;
#pragma unroll
            for (int kk = 0; kk < 2; ++kk) {
                unsigned ahf[2][4];
                int gA = kk * 2 + gsel;
#pragma unroll
                for (int mi = 0; mi < 2; ++mi) {
                    int R = arow + mi * 16;
                    LDSM_X4(ahf[mi], aa + swzA(R, gA));
                }
                int rB = kk * 16 + brow;
#pragma unroll
                for (int n2 = 0; n2 < 4; ++n2) {
                    int gB = wn * 8 + n2 * 2 + gsel;
                    unsigned boff = swz(rB, gB);
                    unsigned bhf[4];
                    LDSM_X4T(bhf, bb + boff);
#pragma unroll
                    for (int mi = 0; mi < 2; ++mi) {
                        mma16816(acc[mi][n2 * 2],     ahf[mi], bhf);
                        mma16816(acc[mi][n2 * 2 + 1], ahf[mi], bhf + 2);
                    }
                }
            }
        }

        // epilogue: unified fp16 scatter to stage dst slots
        const int* sd = (const int*)(dsm + SM_SD + p * 512);
#pragma unroll
        for (int mi = 0; mi < 2; ++mi)
#pragma unroll
            for (int ni = 0; ni < 8; ++ni) {
                int c = wn * 64 + ni * 8 + gc;
                int r0 = wm * 32 + mi * 16 + gr;
                if (r0 < rows)
                    *(__half2*)(Ystage + (size_t)sd[r0] * CCH + c) =
                        __floats2half2_rn(acc[mi][ni][0], acc[mi][ni][1]);
                int r1 = r0 + 8;
                if (r1 < rows)
                    *(__half2*)(Ystage + (size_t)sd[r1] * CCH + c) =
                        __floats2half2_rn(acc[mi][ni][2], acc[mi][ni][3]);
            }
    }
}

// ---------------- combine staged rows -> fp16 y + BN stats -----------------------
__global__ void __launch_bounds__(256) k_combine(__half* __restrict__ Y) {
    __shared__ float red[8][CCH];
    int warp = threadIdx.x >> 5, lane = threadIdx.x & 31;
    float s[4] = {0.f, 0.f, 0.f, 0.f}, s2[4] = {0.f, 0.f, 0.f, 0.f};
    int vbase = blockIdx.x * 64 + warp * 8;
    for (int tt = 0; tt < 8; ++tt) {
        int v = vbase + tt;
        int degp = g_deg[v] + 1;
        float4 acc = make_float4(0.f, 0.f, 0.f, 0.f);
        const __half2* base = (const __half2*)(g_stage + (size_t)v * 27 * CCH + lane * 4);
        for (int q = 0; q < degp; ++q) {
            const __half2* p = base + q * (CCH / 2);
            float2 a = __half22float2(p[0]);
            float2 b = __half22float2(p[1]);
            acc.x += a.x; acc.y += a.y; acc.z += b.x; acc.w += b.y;
        }
        __half2* yv = (__half2*)(Y + (size_t)v * CCH);
        yv[lane * 2]     = __floats2half2_rn(acc.x, acc.y);
        yv[lane * 2 + 1] = __floats2half2_rn(acc.z, acc.w);
        s[0] += acc.x; s[1] += acc.y; s[2] += acc.z; s[3] += acc.w;
        s2[0] += acc.x * acc.x; s2[1] += acc.y * acc.y;
        s2[2] += acc.z * acc.z; s2[3] += acc.w * acc.w;
    }
#pragma unroll
    for (int q = 0; q < 4; ++q) red[warp][lane * 4 + q] = s[q];
    __syncthreads();
    if (threadIdx.x < CCH) {
        float tot = 0.f;
#pragma unroll
        for (int w = 0; w < 8; ++w) tot += red[w][threadIdx.x];
        atomicAdd(&g_sum[threadIdx.x], tot);
    }
    __syncthreads();
#pragma unroll
    for (int q = 0; q < 4; ++q) red[warp][lane * 4 + q] = s2[q];
    __syncthreads();
    if (threadIdx.x < CCH) {
        float tot = 0.f;
#pragma unroll
        for (int w = 0; w < 8; ++w) tot += red[w][threadIdx.x];
        atomicAdd(&g_sumsq[threadIdx.x], tot);
    }
}

// ---------------- activations (BN finalize fused in-block) --------------------------
__global__ void k_act_inner(const __half* __restrict__ Y,
                            const float* __restrict__ gma, const float* __restrict__ bta,
                            __half* __restrict__ X) {
    __shared__ float ssc[CCH], ssh[CCH];
    if (threadIdx.x < CCH) {
        float mu = g_sum[threadIdx.x] * (1.0f / N_VOX);
        float var = g_sumsq[threadIdx.x] * (1.0f / N_VOX) - mu * mu;
        float rs = rsqrtf(var + EPSF);
        float sc = gma[threadIdx.x] * rs;
        ssc[threadIdx.x] = sc;
        ssh[threadIdx.x] = bta[threadIdx.x] - mu * sc;
    }
    __syncthreads();
    int idx = blockIdx.x * blockDim.x + threadIdx.x;
    int c4 = (idx & 31) << 2;
    const __half2* yv = (const __half2*)(Y + (size_t)idx * 4);
    float2 y0 = __half22float2(yv[0]), y1 = __half22float2(yv[1]);
    float4 sc = *(const float4*)(ssc + c4);
    float4 sh = *(const float4*)(ssh + c4);
    float4 v;
    v.x = fmaf(y0.x, sc.x, sh.x);
    v.y = fmaf(y0.y, sc.y, sh.y);
    v.z = fmaf(y1.x, sc.z, sh.z);
    v.w = fmaf(y1.y, sc.w, sh.w);
    v.x = v.x >= 0.f ? v.x : SLOPE_IN * v.x;
    v.y = v.y >= 0.f ? v.y : SLOPE_IN * v.y;
    v.z = v.z >= 0.f ? v.z : SLOPE_IN * v.z;
    v.w = v.w >= 0.f ? v.w : SLOPE_IN * v.w;
    __half2* x = (__half2*)X;
    x[idx * 2]     = __floats2half2_rn(v.x, v.y);
    x[idx * 2 + 1] = __floats2half2_rn(v.z, v.w);
}

__global__ void k_act_out(const __half* __restrict__ Y,
                          const float* __restrict__ gma, const float* __restrict__ bta,
                          const __half* __restrict__ RH, float* __restrict__ O) {
    __shared__ float ssc[CCH], ssh[CCH];
    if (threadIdx.x < CCH) {
        float mu = g_sum[threadIdx.x] * (1.0f / N_VOX);
        float var = g_sumsq[threadIdx.x] * (1.0f / N_VOX) - mu * mu;
        float rs = rsqrtf(var + EPSF);
        float sc = gma[threadIdx.x] * rs;
        ssc[threadIdx.x] = sc;
        ssh[threadIdx.x] = bta[threadIdx.x] - mu * sc;
    }
    __syncthreads();
    int idx = blockIdx.x * blockDim.x + threadIdx.x;
    int c4 = (idx & 31) << 2;
    const __half2* yv = (const __half2*)(Y + (size_t)idx * 4);
    float2 y0 = __half22float2(yv[0]), y1 = __half22float2(yv[1]);
    const __half2* rh = (const __half2*)(RH + (size_t)idx * 4);
    float2 r0 = __half22float2(rh[0]), r1 = __half22float2(rh[1]);
    float4 sc = *(const float4*)(ssc + c4);
    float4 sh = *(const float4*)(ssh + c4);
    float4 v;
    v.x = fmaf(y0.x, sc.x, sh.x) + r0.x;
    v.y = fmaf(y0.y, sc.y, sh.y) + r0.y;
    v.z = fmaf(y1.x, sc.z, sh.z) + r1.x;
    v.w = fmaf(y1.y, sc.w, sh.w) + r1.y;
    v.x = v.x >= 0.f ? v.x : SLOPE_OUT * v.x;
    v.y = v.y >= 0.f ? v.y : SLOPE_OUT * v.y;
    v.z = v.z >= 0.f ? v.z : SLOPE_OUT * v.z;
    v.w = v.w >= 0.f ? v.w : SLOPE_OUT * v.w;
    *(float4*)(O + (size_t)idx * 4) = v;
}

// ---------------- launch ----------------------------------------------------------------
extern "C" void kernel_launch(void* const* d_in, const int* in_sizes, int n_in,
                              void* d_out, int out_size) {
    const float* feat = (const float*)d_in[0];
    const int*   nbr  = (const int*)d_in[1];
    const float* w1   = (const float*)d_in[2];
    const float* w2   = (const float*)d_in[3];
    const float* w3   = (const float*)d_in[4];
    const float* g1   = (const float*)d_in[5];
    const float* b1   = (const float*)d_in[6];
    const float* g2   = (const float*)d_in[7];
    const float* b2   = (const float*)d_in[8];
    const float* g3   = (const float*)d_in[9];
    const float* b3   = (const float*)d_in[10];
    float* out = (float*)d_out;

    __half *p_y, *p_stage, *p_x0, *p_x1, *p_wh;
    cudaGetSymbolAddress((void**)&p_y, g_y);
    cudaGetSymbolAddress((void**)&p_stage, g_stage);
    cudaGetSymbolAddress((void**)&p_x0, g_x0);
    cudaGetSymbolAddress((void**)&p_x1, g_x1);
    cudaGetSymbolAddress((void**)&p_wh, g_wh);

    cudaFuncSetAttribute(conv_mma, cudaFuncAttributeMaxDynamicSharedMemorySize,
                         SMEM_BYTES);

    const int nelem4 = (N_VOX * CCH) / 4;
    const int act_grid = nelem4 / 256;
    const int comb_grid = N_VOX / 64;          // 2048

    // rulebook + operand prep
    k_zero<<<N_VOX / 256, 256>>>();
    k_fill<<<(NK * N_VOX) / 256, 256>>>(nbr);
    k_worklist<<<1, 256>>>();
    {
        dim3 wg(WSZ / 256, 3);
        k_wsplit<<<wg, 256>>>(w1, w2, w3);
    }
    k_xsplit<<<act_grid, 256>>>(feat, p_x0);

    // ---- layer 1 ----
    conv_mma<<<CONV_GRID, 256, SMEM_BYTES>>>(p_x0, p_wh, p_stage);
    k_combine<<<comb_grid, 256>>>(p_y);
    k_act_inner<<<act_grid, 256>>>(p_y, g1, b1, p_x1);   // act1 = residual

    // ---- layer 2 ----
    conv_mma<<<CONV_GRID, 256, SMEM_BYTES>>>(p_x1, p_wh + WSZ, p_stage);
    k_combine<<<comb_grid, 256>>>(p_y);
    k_act_inner<<<act_grid, 256>>>(p_y, g2, b2, p_x0);   // ping-pong

    // ---- layer 3 ----
    conv_mma<<<CONV_GRID, 256, SMEM_BYTES>>>(p_x0, p_wh + 2 * WSZ, p_stage);
    k_combine<<<comb_grid, 256>>>(p_y);
    k_act_out<<<act_grid, 256>>>(p_y, g3, b3, p_x1, out);
}